// round 8
// baseline (speedup 1.0000x reference)
#include <cuda_runtime.h>
#include <cstdint>
#include <cstddef>

#define T_TOK 8192
#define NJ    24
#define NH    8
#define FD    32
#define JD    6144
#define OUTJ  768

__device__ float g_Q[(size_t)T_TOK * JD];   // [t][h][n][f]
__device__ float g_K[(size_t)T_TOK * JD];
__device__ float g_V[(size_t)T_TOK * JD];
__device__ float g_Wt[(size_t)NJ * OUTJ * 256];   // [n][j][d], tf32-rounded
__device__ float g_bias[NJ * OUTJ];

__device__ __forceinline__ uint32_t smem_u32(const void* p) {
    uint32_t a;
    asm("{ .reg .u64 t; cvta.to.shared.u64 t, %1; cvt.u32.u64 %0, t; }" : "=r"(a) : "l"(p));
    return a;
}
__device__ __forceinline__ unsigned f2tf32(float x) {
    unsigned u;
    asm("cvt.rna.tf32.f32 %0, %1;" : "=r"(u) : "f"(x));
    return u;
}
__device__ __forceinline__ void mma_tf32(float* d, const unsigned* a, unsigned b0, unsigned b1) {
    asm volatile(
        "mma.sync.aligned.m16n8k8.row.col.f32.tf32.tf32.f32 "
        "{%0,%1,%2,%3}, {%4,%5,%6,%7}, {%8,%9}, {%0,%1,%2,%3};\n"
        : "+f"(d[0]), "+f"(d[1]), "+f"(d[2]), "+f"(d[3])
        : "r"(a[0]), "r"(a[1]), "r"(a[2]), "r"(a[3]), "r"(b0), "r"(b1));
}
__device__ __forceinline__ void cp16(uint32_t d, const void* s) {
    asm volatile("cp.async.cg.shared.global [%0], [%1], 16;" :: "r"(d), "l"(s));
}
#define CPC()  asm volatile("cp.async.commit_group;" ::: "memory")
#define CPW(n) asm volatile("cp.async.wait_group %0;" :: "n"(n) : "memory")

// ------------------------------- prep ---------------------------------------
__global__ void prep_w_kernel(const float* __restrict__ Wq, const float* __restrict__ Wk,
                              const float* __restrict__ Wv) {
    const size_t total = (size_t)NJ * OUTJ * 256;
    for (size_t i = (size_t)blockIdx.x * blockDim.x + threadIdx.x; i < total;
         i += (size_t)gridDim.x * blockDim.x) {
        int d = (int)(i & 255);
        size_t nj = i >> 8;
        int j = (int)(nj % OUTJ), n = (int)(nj / OUTJ);
        int h = (j >> 5) & 7, f = j & 31;
        float v;
        if (j < 256)      v = Wq[(((size_t)h * NJ + n) * 256 + d) * FD + f];
        else if (j < 512) v = Wk[((size_t)h * 256 + d) * FD + f];
        else              v = Wv[((size_t)h * 256 + d) * FD + f];
        g_Wt[i] = __uint_as_float(f2tf32(v));
    }
}
__global__ void prep_b_kernel(const float* __restrict__ bq, const float* __restrict__ bk,
                              const float* __restrict__ bv) {
    int i = blockIdx.x * blockDim.x + threadIdx.x;
    if (i < NJ * OUTJ) {
        int n = i / OUTJ, j = i % OUTJ, h = (j >> 5) & 7, f = j & 31;
        float v;
        if (j < 256)      v = bq[(h * NJ + n) * FD + f];
        else if (j < 512) v = bk[h * FD + f];
        else              v = bv[h * FD + f];
        g_bias[i] = v;
    }
}

// ------------------ K1: tf32 mma QKV GEMM, staged coalesced epilogue ---------
// 144 CTAs = 24 joints x 6 col-blocks(128). CTA tile 256x128, warps 4m x 2n.
// Crosswise B (one-time permute) -> vector B-fragment loads.
// Epilogue: acc routed through the freed A stage; coalesced STG.128.
#define OFF_B    0
#define OFF_A    131072
#define OFF_BIAS 229376
#define SMEM1    229888

__global__ void __launch_bounds__(256, 1)
qkv_gemm5_kernel(const float* __restrict__ x) {
    extern __shared__ char sm[];
    const uint32_t sb = smem_u32(sm);
    float* bias_s = (float*)(sm + OFF_BIAS);
    const int tid = threadIdx.x, warp = tid >> 5, lane = tid & 31;
    const int g = lane >> 2, tg = lane & 3;
    const int wm = warp >> 1, wn = warp & 1;
    const int nj = blockIdx.x / 6, jb = blockIdx.x % 6;

    // prologue: A chunk0 + chunk1 via cp.async
    {
        const float* xb = x + (size_t)nj * 256;
#pragma unroll
        for (int it = 0; it < 8; ++it) {
            int i = tid + 256 * it;
            int row = i >> 3, c4 = i & 7;
            cp16(sb + OFF_A + (uint32_t)(row * 128 + ((c4 ^ (row & 7)) << 4)),
                 xb + (size_t)row * JD + c4 * 4);
        }
        CPC();
        const float* xb1 = xb + 32;
#pragma unroll
        for (int it = 0; it < 8; ++it) {
            int i = tid + 256 * it;
            int row = i >> 3, c4 = i & 7;
            cp16(sb + OFF_A + 32768u + (uint32_t)(row * 128 + ((c4 ^ (row & 7)) << 4)),
                 xb1 + (size_t)row * JD + c4 * 4);
        }
        CPC();
    }
    // one-time crosswise B permute (resident panel)
    {
        const float4* W4 = (const float4*)(g_Wt + (size_t)(nj * OUTJ + jb * 128) * 256);
        float* Bp = (float*)(sm + OFF_B);
#pragma unroll
        for (int it = 0; it < 32; ++it) {
            int i = tid + 256 * it;            // 8192 float4
            int row = i >> 6, c4 = i & 63;
            float4 v = W4[i];
            int kb = c4 >> 3, k0 = (c4 & 7) * 4;
            float* dst = Bp + row * 256 + kb * 32;
            float e[4] = {v.x, v.y, v.z, v.w};
#pragma unroll
            for (int q = 0; q < 4; ++q) {
                int k = k0 + q;
                int p = (k & 3) * 8 + ((k >> 2) & 1) + ((k >> 3) & 3) * 2;
                int gr = (p >> 2) ^ (row & 7);
                dst[gr * 4 + (p & 3)] = e[q];
            }
        }
        if (tid < 128) bias_s[tid] = g_bias[nj * OUTJ + jb * 128 + tid];
    }
    __syncthreads();

    float acc[4][8][4];
#pragma unroll
    for (int mt = 0; mt < 4; ++mt)
#pragma unroll
        for (int nt = 0; nt < 8; ++nt)
#pragma unroll
            for (int r = 0; r < 4; ++r) acc[mt][nt][r] = 0.f;

    uint32_t aRow[4], bRowOff[8];
#pragma unroll
    for (int mt = 0; mt < 4; ++mt)
        aRow[mt] = (uint32_t)((wm * 64 + mt * 16 + g) * 128 + tg * 4);
#pragma unroll
    for (int nt = 0; nt < 8; ++nt)
        bRowOff[nt] = (uint32_t)(wn * 64 + nt * 8 + g) << 10;
    const uint32_t gr0 = (uint32_t)(((2 * tg) ^ g) << 4);
    const uint32_t gr1 = (uint32_t)(((2 * tg + 1) ^ g) << 4);

#pragma unroll 1
    for (int c = 0; c < 256; ++c) {           // chunk = (mtile c>>3, kb c&7)
        CPW(1);
        __syncthreads();
        if (c + 2 < 256) {
            int cn = c + 2;
            const float* xb = x + (size_t)(cn >> 3) * 256 * JD + (size_t)nj * 256 + (cn & 7) * 32;
            uint32_t stb = sb + OFF_A + (uint32_t)(cn % 3) * 32768u;
#pragma unroll
            for (int it = 0; it < 8; ++it) {
                int i = tid + 256 * it;
                int row = i >> 3, c4 = i & 7;
                cp16(stb + (uint32_t)(row * 128 + ((c4 ^ (row & 7)) << 4)),
                     xb + (size_t)row * JD + c4 * 4);
            }
        }
        CPC();

        const char* A0 = sm + OFF_A + (c % 3) * 32768;
        const char* Bc = sm + OFF_B + (c & 7) * 128;
#pragma unroll
        for (int kp = 0; kp < 2; ++kp) {
            const uint32_t grk = kp ? gr1 : gr0;
            float4 bf[8];
#pragma unroll
            for (int nt = 0; nt < 8; ++nt)
                bf[nt] = *(const float4*)(Bc + bRowOff[nt] + grk);
#pragma unroll
            for (int q = 0; q < 2; ++q) {
                const int kk = 2 * kp + q;
                const uint32_t x0 = (uint32_t)(((2 * kk) ^ g) << 4);
                const uint32_t x1 = (uint32_t)(((2 * kk + 1) ^ g) << 4);
                unsigned a[4][4];
#pragma unroll
                for (int mt = 0; mt < 4; ++mt) {
                    a[mt][0] = *(const unsigned*)(A0 + aRow[mt] + x0);
                    a[mt][1] = *(const unsigned*)(A0 + aRow[mt] + 1024 + x0);
                    a[mt][2] = *(const unsigned*)(A0 + aRow[mt] + x1);
                    a[mt][3] = *(const unsigned*)(A0 + aRow[mt] + 1024 + x1);
                }
#pragma unroll
                for (int mt = 0; mt < 4; ++mt)
#pragma unroll
                    for (int nt = 0; nt < 8; ++nt)
                        mma_tf32(acc[mt][nt], a[mt],
                                 __float_as_uint(q ? bf[nt].z : bf[nt].x),
                                 __float_as_uint(q ? bf[nt].w : bf[nt].y));
            }
        }

        if ((c & 7) == 7) {
            // staged epilogue through the freed A stage (c%3): 4 slices x 64 tokens
            const int mtile = c >> 3;
            char* stg = sm + OFF_A + (c % 3) * 32768;
#pragma unroll 1
            for (int s = 0; s < 4; ++s) {
                if (wm == s) {
                    // owner warps (wn=0,1) stage acc+bias, XOR-swizzled 16B granules
#pragma unroll
                    for (int mt = 0; mt < 4; ++mt)
#pragma unroll
                        for (int nt = 0; nt < 8; ++nt) {
                            int col = wn * 64 + nt * 8 + tg * 2;
                            float b0 = bias_s[col], b1 = bias_s[col + 1];
                            int cg = col >> 2, off = (col & 3) * 4;
                            int r0 = mt * 16 + g, r1 = r0 + 8;
                            *(float2*)(stg + r0 * 512 + ((cg ^ (r0 & 7)) << 4) + off) =
                                make_float2(acc[mt][nt][0] + b0, acc[mt][nt][1] + b1);
                            *(float2*)(stg + r1 * 512 + ((cg ^ (r1 & 7)) << 4) + off) =
                                make_float2(acc[mt][nt][2] + b0, acc[mt][nt][3] + b1);
                            acc[mt][nt][0] = acc[mt][nt][1] = 0.f;
                            acc[mt][nt][2] = acc[mt][nt][3] = 0.f;
                        }
                }
                __syncthreads();
                // all warps: coalesced readout (warp=8 rows, lane=col granule)
                {
                    const int tbase = mtile * 256 + s * 64;
                    const int j = jb * 128 + lane * 4;
                    const int mat = j >> 8, h = (j >> 5) & 7, f = j & 31;
                    float* outp = (mat == 0 ? g_Q : (mat == 1 ? g_K : g_V));
                    const size_t cbase = (size_t)h * OUTJ + nj * 32 + f;
#pragma unroll
                    for (int rr = 0; rr < 8; ++rr) {
                        int row = warp * 8 + rr;
                        float4 v = *(const float4*)(stg + row * 512 + ((lane ^ (row & 7)) << 4));
                        *(float4*)&outp[(size_t)(tbase + row) * JD + cbase] = v;
                    }
                }
                __syncthreads();
            }
        }
    }
}

// -------- K2: 2-CTA/SM attention + residual + LN (R7, proven) ----------------
#define GRID2   296
#define O2_K    0u
#define O2_Q    24576u
#define O2_V    52224u
#define O2_ATT  76800u
#define O2_RED  95232u
#define SMEM2   95488

__global__ void __launch_bounds__(256, 2)
attn_ln5_kernel(const float* __restrict__ x, const float* __restrict__ gamma,
                const float* __restrict__ beta, float* __restrict__ y) {
    extern __shared__ float sm2[];
    float* att = sm2 + (O2_ATT / 4);
    float* red = sm2 + (O2_RED / 4);
    const uint32_t sb = smem_u32(sm2);
    const int tid = threadIdx.x, warp = tid >> 5, lane = tid & 31;
    const int t0 = blockIdx.x;
    const float SC = 0.17677669529663687f;   // 1/sqrt(32)

    {
        const float* Kg = g_K + (size_t)t0 * JD;
        const float* Qg = g_Q + (size_t)t0 * JD;
#pragma unroll
        for (int it = 0; it < 6; ++it) {
            int i = tid + 256 * it;
            cp16(sb + O2_K + (uint32_t)i * 16, Kg + i * 4);
            cp16(sb + O2_Q + (uint32_t)((i >> 3) * 144 + (i & 7) * 16), Qg + i * 4);
        }
        CPC();
        const float* Vg = g_V + (size_t)t0 * JD;
#pragma unroll
        for (int it = 0; it < 6; ++it) {
            int i = tid + 256 * it;
            cp16(sb + O2_V + (uint32_t)i * 16, Vg + i * 4);
        }
        CPC();
    }

#pragma unroll 1
    for (int t = t0; t < T_TOK; t += GRID2) {
        CPW(1);
        __syncthreads();

        if (lane < NJ) {
            const float* qp = sm2 + (O2_Q / 4) + (warp * NJ + lane) * 36;
            float q[32];
#pragma unroll
            for (int f4 = 0; f4 < 8; ++f4) {
                float4 v = *(const float4*)&qp[f4 * 4];
                q[4*f4+0] = v.x * SC; q[4*f4+1] = v.y * SC;
                q[4*f4+2] = v.z * SC; q[4*f4+3] = v.w * SC;
            }
            const float* kp = sm2 + warp * OUTJ;
            float sc[NJ];
#pragma unroll
            for (int m = 0; m < NJ; ++m) {
                const float4* kr = (const float4*)(kp + m * 32);
                float sv = 0.f;
#pragma unroll
                for (int f4 = 0; f4 < 8; ++f4) {
                    float4 kv = kr[f4];
                    sv += q[4*f4+0]*kv.x + q[4*f4+1]*kv.y + q[4*f4+2]*kv.z + q[4*f4+3]*kv.w;
                }
                sc[m] = sv;
            }
            float mx = sc[0];
#pragma unroll
            for (int m = 1; m < NJ; ++m) mx = fmaxf(mx, sc[m]);
            float sum = 0.f;
#pragma unroll
            for (int m = 0; m < NJ; ++m) { sc[m] = __expf(sc[m] - mx); sum += sc[m]; }
            const float inv = 1.f / sum;
            float* ap = att + warp * 576 + lane * 24;
#pragma unroll
            for (int mq = 0; mq < 6; ++mq)
                *(float4*)&ap[mq * 4] = make_float4(sc[4*mq]*inv, sc[4*mq+1]*inv,
                                                   sc[4*mq+2]*inv, sc[4*mq+3]*inv);
        }
        __syncthreads();

        const int tn = t + GRID2;
        if (tn < T_TOK) {
            const float* Kg = g_K + (size_t)tn * JD;
            const float* Qg = g_Q + (size_t)tn * JD;
#pragma unroll
            for (int it = 0; it < 6; ++it) {
                int i = tid + 256 * it;
                cp16(sb + O2_K + (uint32_t)i * 16, Kg + i * 4);
                cp16(sb + O2_Q + (uint32_t)((i >> 3) * 144 + (i & 7) * 16), Qg + i * 4);
            }
        }
        CPC();
        CPW(1);
        __syncthreads();

        float out[NJ];
        {
            const float* xg = x + (size_t)t * JD + tid;
#pragma unroll
            for (int n = 0; n < NJ; ++n) out[n] = xg[n * 256];
        }
        {
            const float* vp = sm2 + (O2_V / 4) + warp * OUTJ + lane;
            const float* ap = att + warp * 576;
#pragma unroll
            for (int mq = 0; mq < 6; ++mq) {
                float v0 = vp[(4*mq+0) * 32];
                float v1 = vp[(4*mq+1) * 32];
                float v2 = vp[(4*mq+2) * 32];
                float v3 = vp[(4*mq+3) * 32];
#pragma unroll
                for (int n = 0; n < NJ; ++n) {
                    float4 a = *(const float4*)&ap[n * 24 + mq * 4];
                    out[n] += a.x*v0 + a.y*v1 + a.z*v2 + a.w*v3;
                }
            }
        }
        float s1 = 0.f, s2 = 0.f;
#pragma unroll
        for (int n = 0; n < NJ; ++n) { s1 += out[n]; s2 += out[n] * out[n]; }
#pragma unroll
        for (int o = 16; o; o >>= 1) {
            s1 += __shfl_xor_sync(0xffffffffu, s1, o);
            s2 += __shfl_xor_sync(0xffffffffu, s2, o);
        }
        if (lane == 0) { red[warp] = s1; red[8 + warp] = s2; }
        __syncthreads();

        if (tn < T_TOK) {
            const float* Vg = g_V + (size_t)tn * JD;
#pragma unroll
            for (int it = 0; it < 6; ++it) {
                int i = tid + 256 * it;
                cp16(sb + O2_V + (uint32_t)i * 16, Vg + i * 4);
            }
        }
        CPC();

        float S1 = 0.f, S2 = 0.f;
#pragma unroll
        for (int w = 0; w < 8; ++w) { S1 += red[w]; S2 += red[8 + w]; }
        const float mu = S1 * (1.0f / JD);
        const float var = S2 * (1.0f / JD) - mu * mu;
        const float rstd = rsqrtf(var + 1e-5f);
        {
            float* yt = y + (size_t)t * JD + tid;
            const float* gp = gamma + tid;
            const float* bp = beta + tid;
#pragma unroll
            for (int n = 0; n < NJ; ++n)
                yt[n * 256] = (out[n] - mu) * rstd * gp[n * 256] + bp[n * 256];
        }
    }
}

// ---------------------------------------------------------------------------
extern "C" void kernel_launch(void* const* d_in, const int* in_sizes, int n_in,
                              void* d_out, int out_size) {
    const float* x     = (const float*)d_in[0];
    const float* Wq    = (const float*)d_in[1];
    const float* bq    = (const float*)d_in[2];
    const float* Wk    = (const float*)d_in[3];
    const float* bk    = (const float*)d_in[4];
    const float* Wv    = (const float*)d_in[5];
    const float* bv    = (const float*)d_in[6];
    const float* gamma = (const float*)d_in[7];
    const float* beta  = (const float*)d_in[8];
    float* y = (float*)d_out;

    cudaFuncSetAttribute(qkv_gemm5_kernel, cudaFuncAttributeMaxDynamicSharedMemorySize, SMEM1);
    cudaFuncSetAttribute(attn_ln5_kernel,  cudaFuncAttributeMaxDynamicSharedMemorySize, SMEM2);

    prep_w_kernel<<<4608, 256>>>(Wq, Wk, Wv);
    prep_b_kernel<<<72, 256>>>(bq, bk, bv);
    qkv_gemm5_kernel<<<NJ * 6, 256, SMEM1>>>(x);
    attn_ln5_kernel<<<GRID2, 256, SMEM2>>>(x, gamma, beta, y);
}

// round 9
// speedup vs baseline: 1.0146x; 1.0146x over previous
#include <cuda_runtime.h>
#include <cstdint>
#include <cstddef>

#define T_TOK 8192
#define NJ    24
#define NH    8
#define FD    32
#define JD    6144
#define OUTJ  768

__device__ float g_Q[(size_t)T_TOK * JD];   // [t][h][n][f]
__device__ float g_K[(size_t)T_TOK * JD];
__device__ float g_V[(size_t)T_TOK * JD];
__device__ float g_Wt[(size_t)NJ * OUTJ * 256];   // [n][j][d], tf32-rounded
__device__ float g_bias[NJ * OUTJ];

__device__ __forceinline__ uint32_t smem_u32(const void* p) {
    uint32_t a;
    asm("{ .reg .u64 t; cvta.to.shared.u64 t, %1; cvt.u32.u64 %0, t; }" : "=r"(a) : "l"(p));
    return a;
}
__device__ __forceinline__ unsigned f2tf32(float x) {
    unsigned u;
    asm("cvt.rna.tf32.f32 %0, %1;" : "=r"(u) : "f"(x));
    return u;
}
__device__ __forceinline__ void mma_tf32(float* d, const unsigned* a, unsigned b0, unsigned b1) {
    asm volatile(
        "mma.sync.aligned.m16n8k8.row.col.f32.tf32.tf32.f32 "
        "{%0,%1,%2,%3}, {%4,%5,%6,%7}, {%8,%9}, {%0,%1,%2,%3};\n"
        : "+f"(d[0]), "+f"(d[1]), "+f"(d[2]), "+f"(d[3])
        : "r"(a[0]), "r"(a[1]), "r"(a[2]), "r"(a[3]), "r"(b0), "r"(b1));
}
__device__ __forceinline__ void cp16(uint32_t d, const void* s) {
    asm volatile("cp.async.cg.shared.global [%0], [%1], 16;" :: "r"(d), "l"(s));
}
#define CPC()  asm volatile("cp.async.commit_group;" ::: "memory")
#define CPW(n) asm volatile("cp.async.wait_group %0;" :: "n"(n) : "memory")

// ------------------------------- prep ---------------------------------------
__global__ void prep_w_kernel(const float* __restrict__ Wq, const float* __restrict__ Wk,
                              const float* __restrict__ Wv) {
    const size_t total = (size_t)NJ * OUTJ * 256;
    for (size_t i = (size_t)blockIdx.x * blockDim.x + threadIdx.x; i < total;
         i += (size_t)gridDim.x * blockDim.x) {
        int d = (int)(i & 255);
        size_t nj = i >> 8;
        int j = (int)(nj % OUTJ), n = (int)(nj / OUTJ);
        int h = (j >> 5) & 7, f = j & 31;
        float v;
        if (j < 256)      v = Wq[(((size_t)h * NJ + n) * 256 + d) * FD + f];
        else if (j < 512) v = Wk[((size_t)h * 256 + d) * FD + f];
        else              v = Wv[((size_t)h * 256 + d) * FD + f];
        g_Wt[i] = __uint_as_float(f2tf32(v));
    }
}
__global__ void prep_b_kernel(const float* __restrict__ bq, const float* __restrict__ bk,
                              const float* __restrict__ bv) {
    int i = blockIdx.x * blockDim.x + threadIdx.x;
    if (i < NJ * OUTJ) {
        int n = i / OUTJ, j = i % OUTJ, h = (j >> 5) & 7, f = j & 31;
        float v;
        if (j < 256)      v = bq[(h * NJ + n) * FD + f];
        else if (j < 512) v = bk[h * FD + f];
        else              v = bv[h * FD + f];
        g_bias[i] = v;
    }
}

// ------------------ K1: tf32 mma QKV GEMM (R7 proven config) -----------------
// 144 CTAs = 24 joints x 6 col-blocks(128). CTA tile 256x128, warps 4m x 2n.
// Crosswise B (one-time permute) -> vector B-fragment loads. Direct epilogue.
#define OFF_B    0
#define OFF_A    131072
#define OFF_BIAS 229376
#define SMEM1    229888

__global__ void __launch_bounds__(256, 1)
qkv_gemm4_kernel(const float* __restrict__ x) {
    extern __shared__ char sm[];
    const uint32_t sb = smem_u32(sm);
    float* bias_s = (float*)(sm + OFF_BIAS);
    const int tid = threadIdx.x, warp = tid >> 5, lane = tid & 31;
    const int g = lane >> 2, tg = lane & 3;
    const int wm = warp >> 1, wn = warp & 1;
    const int nj = blockIdx.x / 6, jb = blockIdx.x % 6;

    {
        const float* xb = x + (size_t)nj * 256;
#pragma unroll
        for (int it = 0; it < 8; ++it) {
            int i = tid + 256 * it;
            int row = i >> 3, c4 = i & 7;
            cp16(sb + OFF_A + (uint32_t)(row * 128 + ((c4 ^ (row & 7)) << 4)),
                 xb + (size_t)row * JD + c4 * 4);
        }
        CPC();
        const float* xb1 = xb + 32;
#pragma unroll
        for (int it = 0; it < 8; ++it) {
            int i = tid + 256 * it;
            int row = i >> 3, c4 = i & 7;
            cp16(sb + OFF_A + 32768u + (uint32_t)(row * 128 + ((c4 ^ (row & 7)) << 4)),
                 xb1 + (size_t)row * JD + c4 * 4);
        }
        CPC();
    }
    {
        const float4* W4 = (const float4*)(g_Wt + (size_t)(nj * OUTJ + jb * 128) * 256);
        float* Bp = (float*)(sm + OFF_B);
#pragma unroll
        for (int it = 0; it < 32; ++it) {
            int i = tid + 256 * it;            // 8192 float4
            int row = i >> 6, c4 = i & 63;
            float4 v = W4[i];
            int kb = c4 >> 3, k0 = (c4 & 7) * 4;
            float* dst = Bp + row * 256 + kb * 32;
            float e[4] = {v.x, v.y, v.z, v.w};
#pragma unroll
            for (int q = 0; q < 4; ++q) {
                int k = k0 + q;
                int p = (k & 3) * 8 + ((k >> 2) & 1) + ((k >> 3) & 3) * 2;
                int gr = (p >> 2) ^ (row & 7);
                dst[gr * 4 + (p & 3)] = e[q];
            }
        }
        if (tid < 128) bias_s[tid] = g_bias[nj * OUTJ + jb * 128 + tid];
    }
    __syncthreads();

    float acc[4][8][4];
#pragma unroll
    for (int mt = 0; mt < 4; ++mt)
#pragma unroll
        for (int nt = 0; nt < 8; ++nt)
#pragma unroll
            for (int r = 0; r < 4; ++r) acc[mt][nt][r] = 0.f;

    uint32_t aRow[4], bRowOff[8];
#pragma unroll
    for (int mt = 0; mt < 4; ++mt)
        aRow[mt] = (uint32_t)((wm * 64 + mt * 16 + g) * 128 + tg * 4);
#pragma unroll
    for (int nt = 0; nt < 8; ++nt)
        bRowOff[nt] = (uint32_t)(wn * 64 + nt * 8 + g) << 10;
    const uint32_t gr0 = (uint32_t)(((2 * tg) ^ g) << 4);
    const uint32_t gr1 = (uint32_t)(((2 * tg + 1) ^ g) << 4);

#pragma unroll 1
    for (int c = 0; c < 256; ++c) {           // chunk = (mtile c>>3, kb c&7)
        CPW(1);
        __syncthreads();
        if (c + 2 < 256) {
            int cn = c + 2;
            const float* xb = x + (size_t)(cn >> 3) * 256 * JD + (size_t)nj * 256 + (cn & 7) * 32;
            uint32_t stb = sb + OFF_A + (uint32_t)(cn % 3) * 32768u;
#pragma unroll
            for (int it = 0; it < 8; ++it) {
                int i = tid + 256 * it;
                int row = i >> 3, c4 = i & 7;
                cp16(stb + (uint32_t)(row * 128 + ((c4 ^ (row & 7)) << 4)),
                     xb + (size_t)row * JD + c4 * 4);
            }
        }
        CPC();

        const char* A0 = sm + OFF_A + (c % 3) * 32768;
        const char* Bc = sm + OFF_B + (c & 7) * 128;
#pragma unroll
        for (int kp = 0; kp < 2; ++kp) {
            const uint32_t grk = kp ? gr1 : gr0;
            float4 bf[8];
#pragma unroll
            for (int nt = 0; nt < 8; ++nt)
                bf[nt] = *(const float4*)(Bc + bRowOff[nt] + grk);
#pragma unroll
            for (int q = 0; q < 2; ++q) {
                const int kk = 2 * kp + q;
                const uint32_t x0 = (uint32_t)(((2 * kk) ^ g) << 4);
                const uint32_t x1 = (uint32_t)(((2 * kk + 1) ^ g) << 4);
                unsigned a[4][4];
#pragma unroll
                for (int mt = 0; mt < 4; ++mt) {
                    a[mt][0] = *(const unsigned*)(A0 + aRow[mt] + x0);
                    a[mt][1] = *(const unsigned*)(A0 + aRow[mt] + 1024 + x0);
                    a[mt][2] = *(const unsigned*)(A0 + aRow[mt] + x1);
                    a[mt][3] = *(const unsigned*)(A0 + aRow[mt] + 1024 + x1);
                }
#pragma unroll
                for (int mt = 0; mt < 4; ++mt)
#pragma unroll
                    for (int nt = 0; nt < 8; ++nt)
                        mma_tf32(acc[mt][nt], a[mt],
                                 __float_as_uint(q ? bf[nt].z : bf[nt].x),
                                 __float_as_uint(q ? bf[nt].w : bf[nt].y));
            }
        }

        if ((c & 7) == 7) {
            const int rbase = (c >> 3) * 256 + wm * 64 + g;
#pragma unroll
            for (int mt = 0; mt < 4; ++mt)
#pragma unroll
                for (int nt = 0; nt < 8; ++nt) {
                    int jl = wn * 64 + nt * 8 + tg * 2;
                    int jg = jb * 128 + jl;
                    float* outp = (jg < 256) ? g_Q : ((jg < 512) ? g_K : g_V);
                    int h = (jg >> 5) & 7, f = jg & 31;
                    float b0 = bias_s[jl], b1 = bias_s[jl + 1];
                    size_t o0 = (size_t)(rbase + mt * 16) * JD + h * OUTJ + nj * 32 + f;
                    *(float2*)&outp[o0] =
                        make_float2(acc[mt][nt][0] + b0, acc[mt][nt][1] + b1);
                    *(float2*)&outp[o0 + 8 * JD] =
                        make_float2(acc[mt][nt][2] + b0, acc[mt][nt][3] + b1);
                    acc[mt][nt][0] = acc[mt][nt][1] = acc[mt][nt][2] = acc[mt][nt][3] = 0.f;
                }
        }
    }
}

// -------- K2: 3-CTA/SM attention + residual + LN, K/V direct from gmem -------
// 444 persistent CTAs x 256 thr. Only Q staged (cp.async transpose-stage);
// K reads are broadcast LDG (1 line/instr), V reads coalesced (1 line/instr).
#define GRID2   444
#define O2_Q    0u          // 192 rows x 36 f = 27648 B
#define O2_ATT  27648u      // 8*24*24 f = 18432 B
#define O2_RED  46080u      // 64 f
#define SMEM2   46336

__global__ void __launch_bounds__(256, 3)
attn_ln6_kernel(const float* __restrict__ x, const float* __restrict__ gamma,
                const float* __restrict__ beta, float* __restrict__ y) {
    extern __shared__ float sm2[];
    float* att = sm2 + (O2_ATT / 4);
    float* red = sm2 + (O2_RED / 4);
    const uint32_t sb = smem_u32(sm2);
    const int tid = threadIdx.x, warp = tid >> 5, lane = tid & 31;
    const int t0 = blockIdx.x;
    const float SC = 0.17677669529663687f;   // 1/sqrt(32)

    // prologue: Q(t0) -> padded stage
    {
        const float* Qg = g_Q + (size_t)t0 * JD;
#pragma unroll
        for (int it = 0; it < 6; ++it) {
            int i = tid + 256 * it;          // 1536 float4
            cp16(sb + O2_Q + (uint32_t)((i >> 3) * 144 + (i & 7) * 16), Qg + i * 4);
        }
        CPC();
    }

#pragma unroll 1
    for (int t = t0; t < T_TOK; t += GRID2) {
        CPW(0);
        __syncthreads();                     // Q(t) staged; prev iter fully done

        // ---- Phase C: scores + softmax (warp=head, lane=joint) ----
        if (lane < NJ) {
            float* ap = att + warp * 576 + lane * 24;
            {   // pass 1: raw scores -> att (q[32] live, sc not)
                const float* qp = sm2 + (warp * NJ + lane) * 36;
                float q[32];
#pragma unroll
                for (int f4 = 0; f4 < 8; ++f4) {
                    float4 v = *(const float4*)&qp[f4 * 4];
                    q[4*f4+0] = v.x * SC; q[4*f4+1] = v.y * SC;
                    q[4*f4+2] = v.z * SC; q[4*f4+3] = v.w * SC;
                }
                const float* kp = g_K + (size_t)t * JD + warp * OUTJ;
#pragma unroll
                for (int m = 0; m < NJ; ++m) {
                    const float4* kr = (const float4*)(kp + m * 32);   // broadcast LDG
                    float sv = 0.f;
#pragma unroll
                    for (int f4 = 0; f4 < 8; ++f4) {
                        float4 kv = kr[f4];
                        sv += q[4*f4+0]*kv.x + q[4*f4+1]*kv.y
                            + q[4*f4+2]*kv.z + q[4*f4+3]*kv.w;
                    }
                    ap[m] = sv;
                }
            }
            {   // pass 2: softmax in place (sc[24] live, q not)
                float sc[NJ];
#pragma unroll
                for (int mq = 0; mq < 6; ++mq) {
                    float4 v = *(const float4*)&ap[mq * 4];
                    sc[4*mq+0] = v.x; sc[4*mq+1] = v.y; sc[4*mq+2] = v.z; sc[4*mq+3] = v.w;
                }
                float mx = sc[0];
#pragma unroll
                for (int m = 1; m < NJ; ++m) mx = fmaxf(mx, sc[m]);
                float sum = 0.f;
#pragma unroll
                for (int m = 0; m < NJ; ++m) { sc[m] = __expf(sc[m] - mx); sum += sc[m]; }
                const float inv = 1.f / sum;
#pragma unroll
                for (int mq = 0; mq < 6; ++mq)
                    *(float4*)&ap[mq * 4] = make_float4(sc[4*mq]*inv, sc[4*mq+1]*inv,
                                                       sc[4*mq+2]*inv, sc[4*mq+3]*inv);
            }
        }
        __syncthreads();                     // att visible; Q stage free

        const int tn = t + GRID2;
        if (tn < T_TOK) {                    // prefetch Q(t+1) — overlaps phase E
            const float* Qg = g_Q + (size_t)tn * JD;
#pragma unroll
            for (int it = 0; it < 6; ++it) {
                int i = tid + 256 * it;
                cp16(sb + O2_Q + (uint32_t)((i >> 3) * 144 + (i & 7) * 16), Qg + i * 4);
            }
        }
        CPC();

        // ---- Phase E: AV + residual (thread = channel (h,f)) ----
        float out[NJ];
        {
            const float* xg = x + (size_t)t * JD + tid;
#pragma unroll
            for (int n = 0; n < NJ; ++n) out[n] = xg[n * 256];
        }
        {
            const float* vp = g_V + (size_t)t * JD + warp * OUTJ + lane;  // coalesced
            const float* ap = att + warp * 576;
#pragma unroll
            for (int mq = 0; mq < 6; ++mq) {
                float v0 = vp[(4*mq+0) * 32];
                float v1 = vp[(4*mq+1) * 32];
                float v2 = vp[(4*mq+2) * 32];
                float v3 = vp[(4*mq+3) * 32];
#pragma unroll
                for (int n = 0; n < NJ; ++n) {
                    float4 a = *(const float4*)&ap[n * 24 + mq * 4];
                    out[n] += a.x*v0 + a.y*v1 + a.z*v2 + a.w*v3;
                }
            }
        }
        // ---- LN over 6144 ----
        float s1 = 0.f, s2 = 0.f;
#pragma unroll
        for (int n = 0; n < NJ; ++n) { s1 += out[n]; s2 += out[n] * out[n]; }
#pragma unroll
        for (int o = 16; o; o >>= 1) {
            s1 += __shfl_xor_sync(0xffffffffu, s1, o);
            s2 += __shfl_xor_sync(0xffffffffu, s2, o);
        }
        if (lane == 0) { red[warp] = s1; red[8 + warp] = s2; }
        __syncthreads();
        float S1 = 0.f, S2 = 0.f;
#pragma unroll
        for (int w = 0; w < 8; ++w) { S1 += red[w]; S2 += red[8 + w]; }
        const float mu = S1 * (1.0f / JD);
        const float var = S2 * (1.0f / JD) - mu * mu;
        const float rstd = rsqrtf(var + 1e-5f);
        {
            float* yt = y + (size_t)t * JD + tid;
            const float* gp = gamma + tid;
            const float* bp = beta + tid;
#pragma unroll
            for (int n = 0; n < NJ; ++n)
                yt[n * 256] = (out[n] - mu) * rstd * gp[n * 256] + bp[n * 256];
        }
    }
}

// ---------------------------------------------------------------------------
extern "C" void kernel_launch(void* const* d_in, const int* in_sizes, int n_in,
                              void* d_out, int out_size) {
    const float* x     = (const float*)d_in[0];
    const float* Wq    = (const float*)d_in[1];
    const float* bq    = (const float*)d_in[2];
    const float* Wk    = (const float*)d_in[3];
    const float* bk    = (const float*)d_in[4];
    const float* Wv    = (const float*)d_in[5];
    const float* bv    = (const float*)d_in[6];
    const float* gamma = (const float*)d_in[7];
    const float* beta  = (const float*)d_in[8];
    float* y = (float*)d_out;

    cudaFuncSetAttribute(qkv_gemm4_kernel, cudaFuncAttributeMaxDynamicSharedMemorySize, SMEM1);
    cudaFuncSetAttribute(attn_ln6_kernel,  cudaFuncAttributeMaxDynamicSharedMemorySize, SMEM2);

    prep_w_kernel<<<4608, 256>>>(Wq, Wk, Wv);
    prep_b_kernel<<<72, 256>>>(bq, bk, bv);
    qkv_gemm4_kernel<<<NJ * 6, 256, SMEM1>>>(x);
    attn_ln6_kernel<<<GRID2, 256, SMEM2>>>(x, gamma, beta, y);
}

// round 10
// speedup vs baseline: 1.2746x; 1.2562x over previous
#include <cuda_runtime.h>
#include <cuda_fp16.h>
#include <cstdint>
#include <cstddef>

#define T_TOK 8192
#define NJ    24
#define NH    8
#define FD    32
#define JD    6144
#define OUTJ  768

__device__ float g_Q[(size_t)T_TOK * JD];   // [t][h][n][f]
__device__ float g_K[(size_t)T_TOK * JD];
__device__ float g_V[(size_t)T_TOK * JD];
__device__ __half g_xh[(size_t)T_TOK * JD];        // x in fp16
__device__ __half g_Wh[(size_t)NJ * OUTJ * 256];   // [n][j][d] fp16
__device__ float g_bias[NJ * OUTJ];

__device__ __forceinline__ uint32_t smem_u32(const void* p) {
    uint32_t a;
    asm("{ .reg .u64 t; cvta.to.shared.u64 t, %1; cvt.u32.u64 %0, t; }" : "=r"(a) : "l"(p));
    return a;
}
__device__ __forceinline__ void mma_f16(float* d, const unsigned* a, unsigned b0, unsigned b1) {
    asm volatile(
        "mma.sync.aligned.m16n8k16.row.col.f32.f16.f16.f32 "
        "{%0,%1,%2,%3}, {%4,%5,%6,%7}, {%8,%9}, {%0,%1,%2,%3};\n"
        : "+f"(d[0]), "+f"(d[1]), "+f"(d[2]), "+f"(d[3])
        : "r"(a[0]), "r"(a[1]), "r"(a[2]), "r"(a[3]), "r"(b0), "r"(b1));
}
__device__ __forceinline__ void cp16(uint32_t d, const void* s) {
    asm volatile("cp.async.cg.shared.global [%0], [%1], 16;" :: "r"(d), "l"(s));
}
#define CPC()  asm volatile("cp.async.commit_group;" ::: "memory")
#define CPW(n) asm volatile("cp.async.wait_group %0;" :: "n"(n) : "memory")

// ------------------------------- prep ---------------------------------------
__global__ void prep_x_kernel(const float* __restrict__ x) {
    size_t i = (size_t)blockIdx.x * blockDim.x + threadIdx.x;   // one per 8 floats
    const size_t total8 = (size_t)T_TOK * JD / 8;
    if (i < total8) {
        float4 v0 = ((const float4*)x)[2 * i];
        float4 v1 = ((const float4*)x)[2 * i + 1];
        __half2 h0 = __floats2half2_rn(v0.x, v0.y);
        __half2 h1 = __floats2half2_rn(v0.z, v0.w);
        __half2 h2 = __floats2half2_rn(v1.x, v1.y);
        __half2 h3 = __floats2half2_rn(v1.z, v1.w);
        uint4 o;
        o.x = *(uint32_t*)&h0; o.y = *(uint32_t*)&h1;
        o.z = *(uint32_t*)&h2; o.w = *(uint32_t*)&h3;
        ((uint4*)g_xh)[i] = o;
    }
}
__global__ void prep_w_kernel(const float* __restrict__ Wq, const float* __restrict__ Wk,
                              const float* __restrict__ Wv) {
    const size_t total = (size_t)NJ * OUTJ * 256;
    for (size_t i = (size_t)blockIdx.x * blockDim.x + threadIdx.x; i < total;
         i += (size_t)gridDim.x * blockDim.x) {
        int d = (int)(i & 255);
        size_t nj = i >> 8;
        int j = (int)(nj % OUTJ), n = (int)(nj / OUTJ);
        int h = (j >> 5) & 7, f = j & 31;
        float v;
        if (j < 256)      v = Wq[(((size_t)h * NJ + n) * 256 + d) * FD + f];
        else if (j < 512) v = Wk[((size_t)h * 256 + d) * FD + f];
        else              v = Wv[((size_t)h * 256 + d) * FD + f];
        g_Wh[i] = __float2half_rn(v);
    }
}
__global__ void prep_b_kernel(const float* __restrict__ bq, const float* __restrict__ bk,
                              const float* __restrict__ bv) {
    int i = blockIdx.x * blockDim.x + threadIdx.x;
    if (i < NJ * OUTJ) {
        int n = i / OUTJ, j = i % OUTJ, h = (j >> 5) & 7, f = j & 31;
        float v;
        if (j < 256)      v = bq[(h * NJ + n) * FD + f];
        else if (j < 512) v = bk[h * FD + f];
        else              v = bv[h * FD + f];
        g_bias[i] = v;
    }
}

// ------------------ K1: fp16 mma.m16n8k16 QKV GEMM ---------------------------
// 144 CTAs = 24 joints x 6 col-blocks(128). CTA tile 256x128, warps 4m x 2n.
// A (fp16) rows padded to 80B, B panel (fp16) rows padded to 528B — both
// conflict-free for fragment LDS.32. 3-stage cp.async A pipeline.
#define OFF_B    0          // 128 x 528 = 67584
#define OFF_A    67584      // 3 x 20480 = 61440
#define OFF_BIAS 129024     // 512
#define SMEM1    129536

__global__ void __launch_bounds__(256, 1)
qkv_gemm6_kernel() {
    extern __shared__ char sm[];
    const uint32_t sb = smem_u32(sm);
    float* bias_s = (float*)(sm + OFF_BIAS);
    const int tid = threadIdx.x, warp = tid >> 5, lane = tid & 31;
    const int g = lane >> 2, tg = lane & 3;
    const int wm = warp >> 1, wn = warp & 1;
    const int nj = blockIdx.x / 6, jb = blockIdx.x % 6;

    // prologue group 0: B panel + A chunk 0 ; group 1: A chunk 1
    {
        const __half* W = g_Wh + (size_t)(nj * OUTJ + jb * 128) * 256;
#pragma unroll
        for (int it = 0; it < 16; ++it) {
            int i = tid + 256 * it;            // 4096 granules: row(128) x c4(32)
            int row = i >> 5, c4 = i & 31;
            cp16(sb + OFF_B + (uint32_t)(row * 528 + c4 * 16), W + row * 256 + c4 * 8);
        }
        const __half* xb = g_xh + (size_t)nj * 256;   // mt=0, kb=0
#pragma unroll
        for (int it = 0; it < 4; ++it) {
            int i = tid + 256 * it;            // 1024 granules: row(256) x c4(4)
            int row = i >> 2, c4 = i & 3;
            cp16(sb + OFF_A + (uint32_t)(row * 80 + c4 * 16), xb + (size_t)row * JD + c4 * 8);
        }
        if (tid < 128) bias_s[tid] = g_bias[nj * OUTJ + jb * 128 + tid];
        CPC();
        const __half* xb1 = xb + 32;
#pragma unroll
        for (int it = 0; it < 4; ++it) {
            int i = tid + 256 * it;
            int row = i >> 2, c4 = i & 3;
            cp16(sb + OFF_A + 20480u + (uint32_t)(row * 80 + c4 * 16),
                 xb1 + (size_t)row * JD + c4 * 8);
        }
        CPC();
    }

    float acc[4][8][4];
#pragma unroll
    for (int mt = 0; mt < 4; ++mt)
#pragma unroll
        for (int nt = 0; nt < 8; ++nt)
#pragma unroll
            for (int r = 0; r < 4; ++r) acc[mt][nt][r] = 0.f;

    uint32_t aRow[4], bRow[8];
#pragma unroll
    for (int mt = 0; mt < 4; ++mt)
        aRow[mt] = (uint32_t)((wm * 64 + mt * 16 + g) * 80 + 4 * tg);
#pragma unroll
    for (int nt = 0; nt < 8; ++nt)
        bRow[nt] = (uint32_t)((wn * 64 + nt * 8 + g) * 528 + 4 * tg);

#pragma unroll 1
    for (int c = 0; c < 256; ++c) {           // chunk = (mtile c>>3, kb c&7)
        CPW(1);
        __syncthreads();
        if (c + 2 < 256) {
            int cn = c + 2;
            const __half* xb = g_xh + (size_t)(cn >> 3) * 256 * JD + (size_t)nj * 256 + (cn & 7) * 32;
            uint32_t stb = sb + OFF_A + (uint32_t)(cn % 3) * 20480u;
#pragma unroll
            for (int it = 0; it < 4; ++it) {
                int i = tid + 256 * it;
                int row = i >> 2, c4 = i & 3;
                cp16(stb + (uint32_t)(row * 80 + c4 * 16), xb + (size_t)row * JD + c4 * 8);
            }
        }
        CPC();

        const char* A0 = sm + OFF_A + (c % 3) * 20480;
        const char* Bc = sm + OFF_B + (c & 7) * 64;    // kb * 32 halves = 64B
#pragma unroll
        for (int s = 0; s < 2; ++s) {                  // two k16 steps
            const uint32_t kb = (uint32_t)(s * 32);    // 16 halves = 32B
            unsigned bfr[8][2];
#pragma unroll
            for (int nt = 0; nt < 8; ++nt) {
                bfr[nt][0] = *(const unsigned*)(Bc + bRow[nt] + kb);
                bfr[nt][1] = *(const unsigned*)(Bc + bRow[nt] + kb + 16);
            }
            unsigned a[4][4];
#pragma unroll
            for (int mt = 0; mt < 4; ++mt) {
                const char* ap = A0 + aRow[mt] + kb;
                a[mt][0] = *(const unsigned*)(ap);          // row g,   k 2tg
                a[mt][1] = *(const unsigned*)(ap + 640);    // row g+8
                a[mt][2] = *(const unsigned*)(ap + 16);     // row g,   k 2tg+8
                a[mt][3] = *(const unsigned*)(ap + 656);    // row g+8
            }
#pragma unroll
            for (int mt = 0; mt < 4; ++mt)
#pragma unroll
                for (int nt = 0; nt < 8; ++nt)
                    mma_f16(acc[mt][nt], a[mt], bfr[nt][0], bfr[nt][1]);
        }

        if ((c & 7) == 7) {                    // epilogue for this 256-row m-tile
            const int rbase = (c >> 3) * 256 + wm * 64 + g;
#pragma unroll
            for (int mt = 0; mt < 4; ++mt)
#pragma unroll
                for (int nt = 0; nt < 8; ++nt) {
                    int jl = wn * 64 + nt * 8 + tg * 2;
                    int jg = jb * 128 + jl;
                    float* outp = (jg < 256) ? g_Q : ((jg < 512) ? g_K : g_V);
                    int h = (jg >> 5) & 7, f = jg & 31;
                    float b0 = bias_s[jl], b1 = bias_s[jl + 1];
                    size_t o0 = (size_t)(rbase + mt * 16) * JD + h * OUTJ + nj * 32 + f;
                    *(float2*)&outp[o0] =
                        make_float2(acc[mt][nt][0] + b0, acc[mt][nt][1] + b1);
                    *(float2*)&outp[o0 + 8 * JD] =
                        make_float2(acc[mt][nt][2] + b0, acc[mt][nt][3] + b1);
                    acc[mt][nt][0] = acc[mt][nt][1] = acc[mt][nt][2] = acc[mt][nt][3] = 0.f;
                }
        }
    }
}

// -------- K2: 2-CTA/SM attention + residual + LN (R7, proven 268us) ----------
#define GRID2   296
#define O2_K    0u
#define O2_Q    24576u
#define O2_V    52224u
#define O2_ATT  76800u
#define O2_RED  95232u
#define SMEM2   95488

__global__ void __launch_bounds__(256, 2)
attn_ln5_kernel(const float* __restrict__ x, const float* __restrict__ gamma,
                const float* __restrict__ beta, float* __restrict__ y) {
    extern __shared__ float sm2[];
    float* att = sm2 + (O2_ATT / 4);
    float* red = sm2 + (O2_RED / 4);
    const uint32_t sb = smem_u32(sm2);
    const int tid = threadIdx.x, warp = tid >> 5, lane = tid & 31;
    const int t0 = blockIdx.x;
    const float SC = 0.17677669529663687f;   // 1/sqrt(32)

    {
        const float* Kg = g_K + (size_t)t0 * JD;
        const float* Qg = g_Q + (size_t)t0 * JD;
#pragma unroll
        for (int it = 0; it < 6; ++it) {
            int i = tid + 256 * it;
            cp16(sb + O2_K + (uint32_t)i * 16, Kg + i * 4);
            cp16(sb + O2_Q + (uint32_t)((i >> 3) * 144 + (i & 7) * 16), Qg + i * 4);
        }
        CPC();
        const float* Vg = g_V + (size_t)t0 * JD;
#pragma unroll
        for (int it = 0; it < 6; ++it) {
            int i = tid + 256 * it;
            cp16(sb + O2_V + (uint32_t)i * 16, Vg + i * 4);
        }
        CPC();
    }

#pragma unroll 1
    for (int t = t0; t < T_TOK; t += GRID2) {
        CPW(1);
        __syncthreads();

        if (lane < NJ) {
            const float* qp = sm2 + (O2_Q / 4) + (warp * NJ + lane) * 36;
            float q[32];
#pragma unroll
            for (int f4 = 0; f4 < 8; ++f4) {
                float4 v = *(const float4*)&qp[f4 * 4];
                q[4*f4+0] = v.x * SC; q[4*f4+1] = v.y * SC;
                q[4*f4+2] = v.z * SC; q[4*f4+3] = v.w * SC;
            }
            const float* kp = sm2 + warp * OUTJ;
            float sc[NJ];
#pragma unroll
            for (int m = 0; m < NJ; ++m) {
                const float4* kr = (const float4*)(kp + m * 32);
                float sv = 0.f;
#pragma unroll
                for (int f4 = 0; f4 < 8; ++f4) {
                    float4 kv = kr[f4];
                    sv += q[4*f4+0]*kv.x + q[4*f4+1]*kv.y + q[4*f4+2]*kv.z + q[4*f4+3]*kv.w;
                }
                sc[m] = sv;
            }
            float mx = sc[0];
#pragma unroll
            for (int m = 1; m < NJ; ++m) mx = fmaxf(mx, sc[m]);
            float sum = 0.f;
#pragma unroll
            for (int m = 0; m < NJ; ++m) { sc[m] = __expf(sc[m] - mx); sum += sc[m]; }
            const float inv = 1.f / sum;
            float* ap = att + warp * 576 + lane * 24;
#pragma unroll
            for (int mq = 0; mq < 6; ++mq)
                *(float4*)&ap[mq * 4] = make_float4(sc[4*mq]*inv, sc[4*mq+1]*inv,
                                                   sc[4*mq+2]*inv, sc[4*mq+3]*inv);
        }
        __syncthreads();

        const int tn = t + GRID2;
        if (tn < T_TOK) {
            const float* Kg = g_K + (size_t)tn * JD;
            const float* Qg = g_Q + (size_t)tn * JD;
#pragma unroll
            for (int it = 0; it < 6; ++it) {
                int i = tid + 256 * it;
                cp16(sb + O2_K + (uint32_t)i * 16, Kg + i * 4);
                cp16(sb + O2_Q + (uint32_t)((i >> 3) * 144 + (i & 7) * 16), Qg + i * 4);
            }
        }
        CPC();
        CPW(1);
        __syncthreads();

        float out[NJ];
        {
            const float* xg = x + (size_t)t * JD + tid;
#pragma unroll
            for (int n = 0; n < NJ; ++n) out[n] = xg[n * 256];
        }
        {
            const float* vp = sm2 + (O2_V / 4) + warp * OUTJ + lane;
            const float* ap = att + warp * 576;
#pragma unroll
            for (int mq = 0; mq < 6; ++mq) {
                float v0 = vp[(4*mq+0) * 32];
                float v1 = vp[(4*mq+1) * 32];
                float v2 = vp[(4*mq+2) * 32];
                float v3 = vp[(4*mq+3) * 32];
#pragma unroll
                for (int n = 0; n < NJ; ++n) {
                    float4 a = *(const float4*)&ap[n * 24 + mq * 4];
                    out[n] += a.x*v0 + a.y*v1 + a.z*v2 + a.w*v3;
                }
            }
        }
        float s1 = 0.f, s2 = 0.f;
#pragma unroll
        for (int n = 0; n < NJ; ++n) { s1 += out[n]; s2 += out[n] * out[n]; }
#pragma unroll
        for (int o = 16; o; o >>= 1) {
            s1 += __shfl_xor_sync(0xffffffffu, s1, o);
            s2 += __shfl_xor_sync(0xffffffffu, s2, o);
        }
        if (lane == 0) { red[warp] = s1; red[8 + warp] = s2; }
        __syncthreads();

        if (tn < T_TOK) {
            const float* Vg = g_V + (size_t)tn * JD;
#pragma unroll
            for (int it = 0; it < 6; ++it) {
                int i = tid + 256 * it;
                cp16(sb + O2_V + (uint32_t)i * 16, Vg + i * 4);
            }
        }
        CPC();

        float S1 = 0.f, S2 = 0.f;
#pragma unroll
        for (int w = 0; w < 8; ++w) { S1 += red[w]; S2 += red[8 + w]; }
        const float mu = S1 * (1.0f / JD);
        const float var = S2 * (1.0f / JD) - mu * mu;
        const float rstd = rsqrtf(var + 1e-5f);
        {
            float* yt = y + (size_t)t * JD + tid;
            const float* gp = gamma + tid;
            const float* bp = beta + tid;
#pragma unroll
            for (int n = 0; n < NJ; ++n)
                yt[n * 256] = (out[n] - mu) * rstd * gp[n * 256] + bp[n * 256];
        }
    }
}

// ---------------------------------------------------------------------------
extern "C" void kernel_launch(void* const* d_in, const int* in_sizes, int n_in,
                              void* d_out, int out_size) {
    const float* x     = (const float*)d_in[0];
    const float* Wq    = (const float*)d_in[1];
    const float* bq    = (const float*)d_in[2];
    const float* Wk    = (const float*)d_in[3];
    const float* bk    = (const float*)d_in[4];
    const float* Wv    = (const float*)d_in[5];
    const float* bv    = (const float*)d_in[6];
    const float* gamma = (const float*)d_in[7];
    const float* beta  = (const float*)d_in[8];
    float* y = (float*)d_out;

    cudaFuncSetAttribute(qkv_gemm6_kernel, cudaFuncAttributeMaxDynamicSharedMemorySize, SMEM1);
    cudaFuncSetAttribute(attn_ln5_kernel,  cudaFuncAttributeMaxDynamicSharedMemorySize, SMEM2);

    prep_x_kernel<<<24576, 256>>>(x);
    prep_w_kernel<<<4608, 256>>>(Wq, Wk, Wv);
    prep_b_kernel<<<72, 256>>>(bq, bk, bv);
    qkv_gemm6_kernel<<<NJ * 6, 256, SMEM1>>>();
    attn_ln5_kernel<<<GRID2, 256, SMEM2>>>(x, gamma, beta, y);
}

// round 11
// speedup vs baseline: 1.3570x; 1.0647x over previous
#include <cuda_runtime.h>
#include <cuda_fp16.h>
#include <cstdint>
#include <cstddef>

#define T_TOK 8192
#define NJ    24
#define NH    8
#define FD    32
#define JD    6144
#define OUTJ  768

__device__ float g_Q[(size_t)T_TOK * JD];   // [t][h][n][f]
__device__ float g_K[(size_t)T_TOK * JD];
__device__ float g_V[(size_t)T_TOK * JD];
__device__ __half g_xh[(size_t)T_TOK * JD];        // x in fp16
__device__ __half g_Wh[(size_t)NJ * OUTJ * 256];   // [n][j][d] fp16
__device__ float g_bias[NJ * OUTJ];

__device__ __forceinline__ uint32_t smem_u32(const void* p) {
    uint32_t a;
    asm("{ .reg .u64 t; cvta.to.shared.u64 t, %1; cvt.u32.u64 %0, t; }" : "=r"(a) : "l"(p));
    return a;
}
__device__ __forceinline__ void mma_f16(float* d, const unsigned* a, unsigned b0, unsigned b1) {
    asm volatile(
        "mma.sync.aligned.m16n8k16.row.col.f32.f16.f16.f32 "
        "{%0,%1,%2,%3}, {%4,%5,%6,%7}, {%8,%9}, {%0,%1,%2,%3};\n"
        : "+f"(d[0]), "+f"(d[1]), "+f"(d[2]), "+f"(d[3])
        : "r"(a[0]), "r"(a[1]), "r"(a[2]), "r"(a[3]), "r"(b0), "r"(b1));
}
__device__ __forceinline__ void cp16(uint32_t d, const void* s) {
    asm volatile("cp.async.cg.shared.global [%0], [%1], 16;" :: "r"(d), "l"(s));
}
#define CPC()  asm volatile("cp.async.commit_group;" ::: "memory")
#define CPW(n) asm volatile("cp.async.wait_group %0;" :: "n"(n) : "memory")

// ------------------------------- prep ---------------------------------------
__global__ void prep_x_kernel(const float* __restrict__ x) {
    size_t i = (size_t)blockIdx.x * blockDim.x + threadIdx.x;   // one per 8 floats
    const size_t total8 = (size_t)T_TOK * JD / 8;
    if (i < total8) {
        float4 v0 = ((const float4*)x)[2 * i];
        float4 v1 = ((const float4*)x)[2 * i + 1];
        __half2 h0 = __floats2half2_rn(v0.x, v0.y);
        __half2 h1 = __floats2half2_rn(v0.z, v0.w);
        __half2 h2 = __floats2half2_rn(v1.x, v1.y);
        __half2 h3 = __floats2half2_rn(v1.z, v1.w);
        uint4 o;
        o.x = *(uint32_t*)&h0; o.y = *(uint32_t*)&h1;
        o.z = *(uint32_t*)&h2; o.w = *(uint32_t*)&h3;
        ((uint4*)g_xh)[i] = o;
    }
}
__global__ void prep_w_kernel(const float* __restrict__ Wq, const float* __restrict__ Wk,
                              const float* __restrict__ Wv) {
    const size_t total = (size_t)NJ * OUTJ * 256;
    for (size_t i = (size_t)blockIdx.x * blockDim.x + threadIdx.x; i < total;
         i += (size_t)gridDim.x * blockDim.x) {
        int d = (int)(i & 255);
        size_t nj = i >> 8;
        int j = (int)(nj % OUTJ), n = (int)(nj / OUTJ);
        int h = (j >> 5) & 7, f = j & 31;
        float v;
        if (j < 256)      v = Wq[(((size_t)h * NJ + n) * 256 + d) * FD + f];
        else if (j < 512) v = Wk[((size_t)h * 256 + d) * FD + f];
        else              v = Wv[((size_t)h * 256 + d) * FD + f];
        g_Wh[i] = __float2half_rn(v);
    }
}
__global__ void prep_b_kernel(const float* __restrict__ bq, const float* __restrict__ bk,
                              const float* __restrict__ bv) {
    int i = blockIdx.x * blockDim.x + threadIdx.x;
    if (i < NJ * OUTJ) {
        int n = i / OUTJ, j = i % OUTJ, h = (j >> 5) & 7, f = j & 31;
        float v;
        if (j < 256)      v = bq[(h * NJ + n) * FD + f];
        else if (j < 512) v = bk[h * FD + f];
        else              v = bv[h * FD + f];
        g_bias[i] = v;
    }
}

// ------------------ K1: fp16 mma.m16n8k16 QKV GEMM, 2 CTAs/SM ----------------
// 288 CTAs = 24 joints x 6 col-blocks(128) x 2 M-halves(4096 rows).
// CTA tile 128x128, 8 warps as 4(m) x 2(n); warp tile 32x64.
// A rows padded 80B, B rows padded 528B (conflict-free). 3-stage cp.async.
#define OFF_B    0          // 128 x 528 = 67584
#define OFF_A    67584      // 3 x 10240 = 30720
#define OFF_BIAS 98304      // 512
#define SMEM1    98816

__global__ void __launch_bounds__(256, 2)
qkv_gemm7_kernel() {
    extern __shared__ char sm[];
    const uint32_t sb = smem_u32(sm);
    float* bias_s = (float*)(sm + OFF_BIAS);
    const int tid = threadIdx.x, warp = tid >> 5, lane = tid & 31;
    const int g = lane >> 2, tg = lane & 3;
    const int wm = warp >> 1, wn = warp & 1;
    const int bx = blockIdx.x;
    const int nj = bx / 12, rem = bx % 12;
    const int jb = rem >> 1, mh = rem & 1;
    const size_t mbase = (size_t)mh * 4096;

    // prologue group 0: B panel + A chunk 0 ; group 1: A chunk 1
    {
        const __half* W = g_Wh + (size_t)(nj * OUTJ + jb * 128) * 256;
#pragma unroll
        for (int it = 0; it < 16; ++it) {
            int i = tid + 256 * it;            // 4096 granules: row(128) x c4(32)
            int row = i >> 5, c4 = i & 31;
            cp16(sb + OFF_B + (uint32_t)(row * 528 + c4 * 16), W + row * 256 + c4 * 8);
        }
        const __half* xb = g_xh + mbase * JD + (size_t)nj * 256;   // mt=0, kb=0
#pragma unroll
        for (int it = 0; it < 2; ++it) {
            int i = tid + 256 * it;            // 512 granules: row(128) x c4(4)
            int row = i >> 2, c4 = i & 3;
            cp16(sb + OFF_A + (uint32_t)(row * 80 + c4 * 16), xb + (size_t)row * JD + c4 * 8);
        }
        if (tid < 128) bias_s[tid] = g_bias[nj * OUTJ + jb * 128 + tid];
        CPC();
        const __half* xb1 = xb + 32;
#pragma unroll
        for (int it = 0; it < 2; ++it) {
            int i = tid + 256 * it;
            int row = i >> 2, c4 = i & 3;
            cp16(sb + OFF_A + 10240u + (uint32_t)(row * 80 + c4 * 16),
                 xb1 + (size_t)row * JD + c4 * 8);
        }
        CPC();
    }

    float acc[2][8][4];
#pragma unroll
    for (int mt = 0; mt < 2; ++mt)
#pragma unroll
        for (int nt = 0; nt < 8; ++nt)
#pragma unroll
            for (int r = 0; r < 4; ++r) acc[mt][nt][r] = 0.f;

    uint32_t aRow[2], bRow[8];
#pragma unroll
    for (int mt = 0; mt < 2; ++mt)
        aRow[mt] = (uint32_t)((wm * 32 + mt * 16 + g) * 80 + 4 * tg);
#pragma unroll
    for (int nt = 0; nt < 8; ++nt)
        bRow[nt] = (uint32_t)((wn * 64 + nt * 8 + g) * 528 + 4 * tg);

#pragma unroll 1
    for (int c = 0; c < 256; ++c) {           // chunk = (mtile c>>3 of 128 rows, kb c&7)
        CPW(1);
        __syncthreads();
        if (c + 2 < 256) {
            int cn = c + 2;
            const __half* xb = g_xh + (mbase + (size_t)(cn >> 3) * 128) * JD +
                               (size_t)nj * 256 + (cn & 7) * 32;
            uint32_t stb = sb + OFF_A + (uint32_t)(cn % 3) * 10240u;
#pragma unroll
            for (int it = 0; it < 2; ++it) {
                int i = tid + 256 * it;
                int row = i >> 2, c4 = i & 3;
                cp16(stb + (uint32_t)(row * 80 + c4 * 16), xb + (size_t)row * JD + c4 * 8);
            }
        }
        CPC();

        const char* A0 = sm + OFF_A + (c % 3) * 10240;
        const char* Bc = sm + OFF_B + (c & 7) * 64;    // kb * 32 halves = 64B
#pragma unroll
        for (int s = 0; s < 2; ++s) {                  // two k16 steps
            const uint32_t kb = (uint32_t)(s * 32);    // 16 halves = 32B
            unsigned bfr[8][2];
#pragma unroll
            for (int nt = 0; nt < 8; ++nt) {
                bfr[nt][0] = *(const unsigned*)(Bc + bRow[nt] + kb);
                bfr[nt][1] = *(const unsigned*)(Bc + bRow[nt] + kb + 16);
            }
            unsigned a[2][4];
#pragma unroll
            for (int mt = 0; mt < 2; ++mt) {
                const char* ap = A0 + aRow[mt] + kb;
                a[mt][0] = *(const unsigned*)(ap);          // row g,   k 2tg
                a[mt][1] = *(const unsigned*)(ap + 640);    // row g+8
                a[mt][2] = *(const unsigned*)(ap + 16);     // row g,   k 2tg+8
                a[mt][3] = *(const unsigned*)(ap + 656);    // row g+8
            }
#pragma unroll
            for (int mt = 0; mt < 2; ++mt)
#pragma unroll
                for (int nt = 0; nt < 8; ++nt)
                    mma_f16(acc[mt][nt], a[mt], bfr[nt][0], bfr[nt][1]);
        }

        if ((c & 7) == 7) {                    // epilogue for this 128-row m-tile
            const int rbase = (int)mbase + (c >> 3) * 128 + wm * 32 + g;
#pragma unroll
            for (int mt = 0; mt < 2; ++mt)
#pragma unroll
                for (int nt = 0; nt < 8; ++nt) {
                    int jl = wn * 64 + nt * 8 + tg * 2;
                    int jg = jb * 128 + jl;
                    float* outp = (jg < 256) ? g_Q : ((jg < 512) ? g_K : g_V);
                    int h = (jg >> 5) & 7, f = jg & 31;
                    float b0 = bias_s[jl], b1 = bias_s[jl + 1];
                    size_t o0 = (size_t)(rbase + mt * 16) * JD + h * OUTJ + nj * 32 + f;
                    *(float2*)&outp[o0] =
                        make_float2(acc[mt][nt][0] + b0, acc[mt][nt][1] + b1);
                    *(float2*)&outp[o0 + 8 * JD] =
                        make_float2(acc[mt][nt][2] + b0, acc[mt][nt][3] + b1);
                    acc[mt][nt][0] = acc[mt][nt][1] = acc[mt][nt][2] = acc[mt][nt][3] = 0.f;
                }
        }
    }
}

// -------- K2: 2-CTA/SM attention + residual + LN (proven 268us) --------------
#define GRID2   296
#define O2_K    0u
#define O2_Q    24576u
#define O2_V    52224u
#define O2_ATT  76800u
#define O2_RED  95232u
#define SMEM2   95488

__global__ void __launch_bounds__(256, 2)
attn_ln5_kernel(const float* __restrict__ x, const float* __restrict__ gamma,
                const float* __restrict__ beta, float* __restrict__ y) {
    extern __shared__ float sm2[];
    float* att = sm2 + (O2_ATT / 4);
    float* red = sm2 + (O2_RED / 4);
    const uint32_t sb = smem_u32(sm2);
    const int tid = threadIdx.x, warp = tid >> 5, lane = tid & 31;
    const int t0 = blockIdx.x;
    const float SC = 0.17677669529663687f;   // 1/sqrt(32)

    {
        const float* Kg = g_K + (size_t)t0 * JD;
        const float* Qg = g_Q + (size_t)t0 * JD;
#pragma unroll
        for (int it = 0; it < 6; ++it) {
            int i = tid + 256 * it;
            cp16(sb + O2_K + (uint32_t)i * 16, Kg + i * 4);
            cp16(sb + O2_Q + (uint32_t)((i >> 3) * 144 + (i & 7) * 16), Qg + i * 4);
        }
        CPC();
        const float* Vg = g_V + (size_t)t0 * JD;
#pragma unroll
        for (int it = 0; it < 6; ++it) {
            int i = tid + 256 * it;
            cp16(sb + O2_V + (uint32_t)i * 16, Vg + i * 4);
        }
        CPC();
    }

#pragma unroll 1
    for (int t = t0; t < T_TOK; t += GRID2) {
        CPW(1);
        __syncthreads();

        if (lane < NJ) {
            const float* qp = sm2 + (O2_Q / 4) + (warp * NJ + lane) * 36;
            float q[32];
#pragma unroll
            for (int f4 = 0; f4 < 8; ++f4) {
                float4 v = *(const float4*)&qp[f4 * 4];
                q[4*f4+0] = v.x * SC; q[4*f4+1] = v.y * SC;
                q[4*f4+2] = v.z * SC; q[4*f4+3] = v.w * SC;
            }
            const float* kp = sm2 + warp * OUTJ;
            float sc[NJ];
#pragma unroll
            for (int m = 0; m < NJ; ++m) {
                const float4* kr = (const float4*)(kp + m * 32);
                float sv = 0.f;
#pragma unroll
                for (int f4 = 0; f4 < 8; ++f4) {
                    float4 kv = kr[f4];
                    sv += q[4*f4+0]*kv.x + q[4*f4+1]*kv.y + q[4*f4+2]*kv.z + q[4*f4+3]*kv.w;
                }
                sc[m] = sv;
            }
            float mx = sc[0];
#pragma unroll
            for (int m = 1; m < NJ; ++m) mx = fmaxf(mx, sc[m]);
            float sum = 0.f;
#pragma unroll
            for (int m = 0; m < NJ; ++m) { sc[m] = __expf(sc[m] - mx); sum += sc[m]; }
            const float inv = 1.f / sum;
            float* ap = att + warp * 576 + lane * 24;
#pragma unroll
            for (int mq = 0; mq < 6; ++mq)
                *(float4*)&ap[mq * 4] = make_float4(sc[4*mq]*inv, sc[4*mq+1]*inv,
                                                   sc[4*mq+2]*inv, sc[4*mq+3]*inv);
        }
        __syncthreads();

        const int tn = t + GRID2;
        if (tn < T_TOK) {
            const float* Kg = g_K + (size_t)tn * JD;
            const float* Qg = g_Q + (size_t)tn * JD;
#pragma unroll
            for (int it = 0; it < 6; ++it) {
                int i = tid + 256 * it;
                cp16(sb + O2_K + (uint32_t)i * 16, Kg + i * 4);
                cp16(sb + O2_Q + (uint32_t)((i >> 3) * 144 + (i & 7) * 16), Qg + i * 4);
            }
        }
        CPC();
        CPW(1);
        __syncthreads();

        float out[NJ];
        {
            const float* xg = x + (size_t)t * JD + tid;
#pragma unroll
            for (int n = 0; n < NJ; ++n) out[n] = xg[n * 256];
        }
        {
            const float* vp = sm2 + (O2_V / 4) + warp * OUTJ + lane;
            const float* ap = att + warp * 576;
#pragma unroll
            for (int mq = 0; mq < 6; ++mq) {
                float v0 = vp[(4*mq+0) * 32];
                float v1 = vp[(4*mq+1) * 32];
                float v2 = vp[(4*mq+2) * 32];
                float v3 = vp[(4*mq+3) * 32];
#pragma unroll
                for (int n = 0; n < NJ; ++n) {
                    float4 a = *(const float4*)&ap[n * 24 + mq * 4];
                    out[n] += a.x*v0 + a.y*v1 + a.z*v2 + a.w*v3;
                }
            }
        }
        float s1 = 0.f, s2 = 0.f;
#pragma unroll
        for (int n = 0; n < NJ; ++n) { s1 += out[n]; s2 += out[n] * out[n]; }
#pragma unroll
        for (int o = 16; o; o >>= 1) {
            s1 += __shfl_xor_sync(0xffffffffu, s1, o);
            s2 += __shfl_xor_sync(0xffffffffu, s2, o);
        }
        if (lane == 0) { red[warp] = s1; red[8 + warp] = s2; }
        __syncthreads();

        if (tn < T_TOK) {
            const float* Vg = g_V + (size_t)tn * JD;
#pragma unroll
            for (int it = 0; it < 6; ++it) {
                int i = tid + 256 * it;
                cp16(sb + O2_V + (uint32_t)i * 16, Vg + i * 4);
            }
        }
        CPC();

        float S1 = 0.f, S2 = 0.f;
#pragma unroll
        for (int w = 0; w < 8; ++w) { S1 += red[w]; S2 += red[8 + w]; }
        const float mu = S1 * (1.0f / JD);
        const float var = S2 * (1.0f / JD) - mu * mu;
        const float rstd = rsqrtf(var + 1e-5f);
        {
            float* yt = y + (size_t)t * JD + tid;
            const float* gp = gamma + tid;
            const float* bp = beta + tid;
#pragma unroll
            for (int n = 0; n < NJ; ++n)
                yt[n * 256] = (out[n] - mu) * rstd * gp[n * 256] + bp[n * 256];
        }
    }
}

// ---------------------------------------------------------------------------
extern "C" void kernel_launch(void* const* d_in, const int* in_sizes, int n_in,
                              void* d_out, int out_size) {
    const float* x     = (const float*)d_in[0];
    const float* Wq    = (const float*)d_in[1];
    const float* bq    = (const float*)d_in[2];
    const float* Wk    = (const float*)d_in[3];
    const float* bk    = (const float*)d_in[4];
    const float* Wv    = (const float*)d_in[5];
    const float* bv    = (const float*)d_in[6];
    const float* gamma = (const float*)d_in[7];
    const float* beta  = (const float*)d_in[8];
    float* y = (float*)d_out;

    cudaFuncSetAttribute(qkv_gemm7_kernel, cudaFuncAttributeMaxDynamicSharedMemorySize, SMEM1);
    cudaFuncSetAttribute(attn_ln5_kernel,  cudaFuncAttributeMaxDynamicSharedMemorySize, SMEM2);

    prep_x_kernel<<<24576, 256>>>(x);
    prep_w_kernel<<<4608, 256>>>(Wq, Wk, Wv);
    prep_b_kernel<<<72, 256>>>(bq, bk, bv);
    qkv_gemm7_kernel<<<288, 256, SMEM1>>>();
    attn_ln5_kernel<<<GRID2, 256, SMEM2>>>(x, gamma, beta, y);
}